// round 15
// baseline (speedup 1.0000x reference)
#include <cuda_runtime.h>
#include <cuda_fp16.h>
#include <cstdint>

// Problem constants
#define B_   4
#define T_   2048
#define E_   1024
#define H_   16
#define HS_  64
#define DFF_ 4096
#define M_   (B_ * T_)   // 8192 rows

// ---------------------------------------------------------------------------
// Scratch (device globals)
// ---------------------------------------------------------------------------
__device__ __half g_a[(size_t)M_ * E_];     // fp16 activations
__device__ __half g_f[(size_t)M_ * DFF_];   // fp16 FFN hidden
__device__ __half g_q[(size_t)M_ * E_], g_k[(size_t)M_ * E_], g_v[(size_t)M_ * E_];
// fp16 transposed weights [N,K]
__device__ __half g_wq[(size_t)E_ * E_], g_wk[(size_t)E_ * E_];
__device__ __half g_wv[(size_t)E_ * E_], g_wp[(size_t)E_ * E_];
__device__ __half g_w1[(size_t)E_ * DFF_], g_w2[(size_t)DFF_ * E_];

// ---------------------------------------------------------------------------
// Helpers
// ---------------------------------------------------------------------------
__device__ __forceinline__ uint32_t smem_u32(const void* p) {
    uint32_t a;
    asm("{ .reg .u64 t; cvta.to.shared.u64 t, %1; cvt.u32.u64 %0, t; }"
        : "=r"(a) : "l"(p));
    return a;
}

__device__ __forceinline__ void ldm_x4(uint32_t* r, uint32_t addr) {
    asm volatile("ldmatrix.sync.aligned.m8n8.x4.shared.b16 {%0,%1,%2,%3}, [%4];"
                 : "=r"(r[0]), "=r"(r[1]), "=r"(r[2]), "=r"(r[3]) : "r"(addr));
}
__device__ __forceinline__ void ldm_x4_t(uint32_t* r, uint32_t addr) {
    asm volatile("ldmatrix.sync.aligned.m8n8.x4.trans.shared.b16 {%0,%1,%2,%3}, [%4];"
                 : "=r"(r[0]), "=r"(r[1]), "=r"(r[2]), "=r"(r[3]) : "r"(addr));
}

__device__ __forceinline__ void mma16816h(float* c, const uint32_t* a, const uint32_t* b) {
    asm volatile(
        "mma.sync.aligned.m16n8k16.row.col.f32.f16.f16.f32 "
        "{%0,%1,%2,%3}, {%4,%5,%6,%7}, {%8,%9}, {%0,%1,%2,%3};"
        : "+f"(c[0]), "+f"(c[1]), "+f"(c[2]), "+f"(c[3])
        : "r"(a[0]), "r"(a[1]), "r"(a[2]), "r"(a[3]), "r"(b[0]), "r"(b[1]));
}

#define CP_ASYNC16(dst, src) \
    asm volatile("cp.async.cg.shared.global [%0], [%1], 16;" :: "r"(dst), "l"(src))
#define CP_COMMIT() asm volatile("cp.async.commit_group;" ::: "memory")
#define CP_WAIT0() asm volatile("cp.async.wait_group 0;" ::: "memory")
#define CP_WAIT1() asm volatile("cp.async.wait_group 1;" ::: "memory")
#define CP_WAIT2() asm volatile("cp.async.wait_group 2;" ::: "memory")

__device__ __forceinline__ uint32_t pack_h2(float a, float b) {
    __half2 h = __floats2half2_rn(a, b);
    return *reinterpret_cast<uint32_t*>(&h);
}

// 128-row x 128-byte K-major tile, SW128 swizzle, 256 threads
__device__ __forceinline__ void cpa_tile128(const __half* __restrict__ g,
                                            int ldk, int k0, uint32_t sbase) {
    int tid = threadIdx.x;
    #pragma unroll
    for (int i = 0; i < 4; i++) {
        int idx = i * 256 + tid;
        int r = idx >> 3, c = idx & 7;
        uint32_t off = (uint32_t)(r * 128 + c * 16);
        off ^= (off >> 3) & 0x70;
        CP_ASYNC16(sbase + off, g + (size_t)r * ldk + k0 + c * 8);
    }
}

// ---------------------------------------------------------------------------
// LN body (shared)
// ---------------------------------------------------------------------------
__device__ __forceinline__ void ln_body(float vx, float vy, float vz, float vw,
                                        const float* __restrict__ gamma,
                                        const float* __restrict__ beta,
                                        __half* __restrict__ O, int row, int t,
                                        float* red) {
    float s1 = vx + vy + vz + vw;
    float s2 = vx * vx + vy * vy + vz * vz + vw * vw;
    #pragma unroll
    for (int o = 16; o > 0; o >>= 1) {
        s1 += __shfl_xor_sync(0xffffffffu, s1, o);
        s2 += __shfl_xor_sync(0xffffffffu, s2, o);
    }
    int lane = t & 31, w = t >> 5;
    if (lane == 0) { red[w] = s1; red[w + 32] = s2; }
    __syncthreads();
    float ts1 = 0.f, ts2 = 0.f;
    #pragma unroll
    for (int i = 0; i < 8; i++) { ts1 += red[i]; ts2 += red[i + 32]; }

    float mu  = ts1 * (1.0f / E_);
    float var = ts2 * (1.0f / E_) - mu * mu;
    float rs  = rsqrtf(var + 1e-5f);

    float4 g4 = ((const float4*)gamma)[t];
    float4 b4 = ((const float4*)beta)[t];
    float o0 = (vx - mu) * rs * g4.x + b4.x;
    float o1 = (vy - mu) * rs * g4.y + b4.y;
    float o2 = (vz - mu) * rs * g4.z + b4.z;
    float o3 = (vw - mu) * rs * g4.w + b4.w;

    size_t idx = (size_t)row * E_ + t * 4;
    *reinterpret_cast<uint2*>(O + idx) = make_uint2(pack_h2(o0, o1), pack_h2(o2, o3));
}

// ---------------------------------------------------------------------------
// Fused prep: blocks [0,3072) = weight transpose+convert; [3072,..) = ln1.
// ---------------------------------------------------------------------------
struct PrepArgs {
    const float* src[6];
    __half* dst[6];
    int K[6], N[6];
    int base[6];
    int nx[6];
    const float* x;
    const float* ln_g;
    const float* ln_b;
    __half* ln_o;
};

#define WT_BLOCKS 3072

__global__ __launch_bounds__(256)
void prep_kernel(PrepArgs a) {
    __shared__ float t[64][65];
    int bid = blockIdx.x;
    int tid = threadIdx.x;

    if (bid >= WT_BLOCKS) {
        int row = bid - WT_BLOCKS;
        float4 v = ((const float4*)(a.x + (size_t)row * E_))[tid];
        ln_body(v.x, v.y, v.z, v.w, a.ln_g, a.ln_b, a.ln_o, row, tid, &t[0][0]);
        return;
    }

    int z = 0;
    #pragma unroll
    for (int i = 1; i < 6; i++)
        if (bid >= a.base[i]) z = i;
    int local = bid - a.base[z];
    int bx = local % a.nx[z];
    int by = local / a.nx[z];
    const float* W = a.src[z];
    __half* T = a.dst[z];
    int K = a.K[z], N = a.N[z];
    int n0 = bx * 64, k0 = by * 64;

    int r = tid >> 2, c0 = (tid & 3) * 16;
    const float4* src = reinterpret_cast<const float4*>(
        W + (size_t)(k0 + r) * N + n0 + c0);
    #pragma unroll
    for (int j = 0; j < 4; j++) {
        float4 v = src[j];
        t[r][c0 + j * 4 + 0] = v.x;
        t[r][c0 + j * 4 + 1] = v.y;
        t[r][c0 + j * 4 + 2] = v.z;
        t[r][c0 + j * 4 + 3] = v.w;
    }
    __syncthreads();

    int nr = tid >> 2;
    uint32_t o8[8];
    #pragma unroll
    for (int j = 0; j < 8; j++)
        o8[j] = pack_h2(t[c0 + 2 * j][nr], t[c0 + 2 * j + 1][nr]);
    __half* dst = T + (size_t)(n0 + nr) * K + k0 + c0;
    *reinterpret_cast<uint4*>(dst)     = make_uint4(o8[0], o8[1], o8[2], o8[3]);
    *reinterpret_cast<uint4*>(dst + 8) = make_uint4(o8[4], o8[5], o8[6], o8[7]);
}

// ---------------------------------------------------------------------------
// LayerNorm fp16-in -> fp16 (residual stream)
// ---------------------------------------------------------------------------
__global__ __launch_bounds__(256)
void ln_h16_kernel(const __half* __restrict__ in, const float* __restrict__ gamma,
                   const float* __restrict__ beta, __half* __restrict__ O) {
    __shared__ float red[64];
    int row = blockIdx.x;
    int t = threadIdx.x;
    uint2 pv = ((const uint2*)(in + (size_t)row * E_))[t];
    float2 f01 = __half22float2(*reinterpret_cast<__half2*>(&pv.x));
    float2 f23 = __half22float2(*reinterpret_cast<__half2*>(&pv.y));
    ln_body(f01.x, f01.y, f23.x, f23.y, gamma, beta, O, row, t, red);
}

// ---------------------------------------------------------------------------
// fp16 GEMM: C[M,N] = A[M,K] @ Wt[N,K]^T + bias (+...)
// 128x128 CTA, BK=64, 8 warps, 3-stage cp.async, 2 CTAs/SM.
// PREFETCH-FIRST ordering: stage kt+2 loads issued right after the barrier,
// before compute — stage (kt+2)%3 == (kt-1)%3 last read in iter kt-1,
// protected by this iteration's barrier.
// EPI: 0 bias->fp16 ; 1 bias+relu->fp16 ; 3 bias+res(fp32)->fp16 ;
//      4 bias+res(fp16)->fp32
// ---------------------------------------------------------------------------
#define HTILE_B  16384
#define HSTAGE_B (2 * HTILE_B)
#define HGSMEM   (3 * HSTAGE_B + 128)

template<int EPI>
__device__ __forceinline__ void gemm_core_h(
        const __half* __restrict__ A, const __half* __restrict__ Bw,
        const float* __restrict__ bias, const float* __restrict__ resf,
        const __half* __restrict__ res16,
        float* __restrict__ Cf, __half* __restrict__ Hh,
        int M, int N, int K, int m0, int n0, uint32_t base) {
    int tid = threadIdx.x, lane = tid & 31, wid = tid >> 5;
    int warp_m = wid >> 2;
    int warp_n = wid & 3;

    const __half* Ab = A  + (size_t)m0 * K;
    const __half* Bb = Bw + (size_t)n0 * K;

    int amat = lane >> 3, arin = lane & 7;
    int aRow = warp_m * 64 + (amat & 1) * 8 + arin;
    int aChk = amat >> 1;
    int bRow4 = warp_n * 32 + ((lane >> 4) & 1) * 8 + (lane & 7);
    int bChk4 = (lane >> 3) & 1;

    float C[4][4][4];
    #pragma unroll
    for (int i = 0; i < 4; i++)
        #pragma unroll
        for (int j = 0; j < 4; j++)
            #pragma unroll
            for (int r = 0; r < 4; r++) C[i][j][r] = 0.f;

    int NT = K >> 6;

    cpa_tile128(Ab, K, 0, base);
    cpa_tile128(Bb, K, 0, base + HTILE_B);
    CP_COMMIT();
    cpa_tile128(Ab, K, 64, base + HSTAGE_B);
    cpa_tile128(Bb, K, 64, base + HSTAGE_B + HTILE_B);
    CP_COMMIT();

    for (int kt = 0; kt < NT; kt++) {
        if (kt + 1 < NT) { CP_WAIT1(); } else { CP_WAIT0(); }
        __syncthreads();

        // prefetch FIRST: maximum latency headroom, LSU/tensor interleave
        if (kt + 2 < NT) {
            uint32_t sn = base + ((kt + 2) % 3) * HSTAGE_B;
            int k0 = (kt + 2) << 6;
            cpa_tile128(Ab, K, k0, sn);
            cpa_tile128(Bb, K, k0, sn + HTILE_B);
            CP_COMMIT();
        }

        uint32_t sc = base + (kt % 3) * HSTAGE_B;
        uint32_t sA = sc, sB = sc + HTILE_B;

        #pragma unroll
        for (int ks = 0; ks < 4; ks++) {
            uint32_t a4[4][4], b4[2][4];
            #pragma unroll
            for (int mi = 0; mi < 4; mi++) {
                uint32_t off = (uint32_t)((aRow + mi * 16) * 128 + (aChk + ks * 2) * 16);
                off ^= (off >> 3) & 0x70;
                ldm_x4(a4[mi], sA + off);
            }
            #pragma unroll
            for (int ni2 = 0; ni2 < 2; ni2++) {
                uint32_t off = (uint32_t)((bRow4 + ni2 * 16) * 128 + (bChk4 + ks * 2) * 16);
                off ^= (off >> 3) & 0x70;
                ldm_x4(b4[ni2], sB + off);
            }
            #pragma unroll
            for (int mi = 0; mi < 4; mi++) {
                #pragma unroll
                for (int ni2 = 0; ni2 < 2; ni2++) {
                    mma16816h(C[mi][2 * ni2],     a4[mi], &b4[ni2][0]);
                    mma16816h(C[mi][2 * ni2 + 1], a4[mi], &b4[ni2][2]);
                }
            }
        }
    }

    int gq = lane >> 2, tig = lane & 3;
    #pragma unroll
    for (int mi = 0; mi < 4; mi++) {
        #pragma unroll
        for (int ni = 0; ni < 4; ni++) {
            int m = m0 + warp_m * 64 + mi * 16 + gq;
            int n = n0 + warp_n * 32 + ni * 8 + tig * 2;
            float2 bv = *reinterpret_cast<const float2*>(&bias[n]);
            #pragma unroll
            for (int half_ = 0; half_ < 2; half_++) {
                int row = m + half_ * 8;
                float a0 = C[mi][ni][half_ * 2 + 0] + bv.x;
                float a1 = C[mi][ni][half_ * 2 + 1] + bv.y;
                size_t o = (size_t)row * N + n;
                if (EPI == 0) {
                    *reinterpret_cast<uint32_t*>(Hh + o) = pack_h2(a0, a1);
                } else if (EPI == 1) {
                    a0 = fmaxf(a0, 0.f); a1 = fmaxf(a1, 0.f);
                    *reinterpret_cast<uint32_t*>(Hh + o) = pack_h2(a0, a1);
                } else if (EPI == 3) {
                    float2 rv = *reinterpret_cast<const float2*>(&resf[o]);
                    a0 += rv.x; a1 += rv.y;
                    *reinterpret_cast<uint32_t*>(Hh + o) = pack_h2(a0, a1);
                } else {  // EPI == 4
                    uint32_t rp = *reinterpret_cast<const uint32_t*>(&res16[o]);
                    float2 rv = __half22float2(*reinterpret_cast<__half2*>(&rp));
                    a0 += rv.x; a1 += rv.y;
                    *reinterpret_cast<float2*>(&Cf[o]) = make_float2(a0, a1);
                }
            }
        }
    }
}

template<int EPI>
__global__ __launch_bounds__(256, 2)
void hgemm_kernel(const __half* __restrict__ A, const __half* __restrict__ Bw,
                  const float* __restrict__ bias, const float* __restrict__ resf,
                  const __half* __restrict__ res16,
                  float* __restrict__ Cf, __half* __restrict__ Hh,
                  int M, int N, int K) {
    extern __shared__ char dsm[];
    uint32_t base = smem_u32(dsm);
    base = (base + 127) & ~127u;
    gemm_core_h<EPI>(A, Bw, bias, resf, res16, Cf, Hh, M, N, K,
                     blockIdx.y * 128, blockIdx.x * 128, base);
}

struct QKVArgs {
    const __half* w[3];
    const float* bias[3];
    __half* o[3];
};

__global__ __launch_bounds__(256, 2)
void qkv_kernel(const __half* __restrict__ A, QKVArgs args) {
    extern __shared__ char dsm[];
    uint32_t base = smem_u32(dsm);
    base = (base + 127) & ~127u;
    int z = blockIdx.z;
    gemm_core_h<0>(A, args.w[z], args.bias[z], nullptr, nullptr, nullptr,
                   args.o[z], M_, E_, E_,
                   blockIdx.y * 128, blockIdx.x * 128, base);
}

// ---------------------------------------------------------------------------
// fp16 tensor-core causal flash attention (R14 config).
// ---------------------------------------------------------------------------
#define AQ_BYTES  16384
#define AST_SZ    32768
#define ATTN_SMEM (AQ_BYTES + 3 * AST_SZ + 128)
#define CEXP 0.18033688011112042f  // 0.125 * log2(e)

__global__ __launch_bounds__(256, 2)
void attn_mma_kernel(const __half* __restrict__ Qg, const __half* __restrict__ Kg,
                     const __half* __restrict__ Vg, __half* __restrict__ O) {
    extern __shared__ char dsm[];
    uint32_t base = smem_u32(dsm);
    base = (base + 127) & ~127u;

    int tid = threadIdx.x, lane = tid & 31, w = tid >> 5;
    int gq = lane >> 2, tig = lane & 3;
    int qi = gridDim.x - 1 - blockIdx.x;
    int q0 = qi * 128;
    int bh = blockIdx.y;
    int b = bh >> 4, h = bh & 15;
    size_t gbase = ((size_t)b * T_) * E_ + (size_t)h * HS_;

    int nt = (q0 >> 7) + 1;

    cpa_tile128(Qg + gbase + (size_t)q0 * E_, E_, 0, base);
    CP_COMMIT();
    int pre = nt < 2 ? nt : 2;
    for (int st = 0; st < pre; st++) {
        uint32_t s = base + AQ_BYTES + st * AST_SZ;
        size_t koff = gbase + (size_t)(st * 128) * E_;
        cpa_tile128(Kg + koff, E_, 0, s);
        cpa_tile128(Vg + koff, E_, 0, s + 16384);
        CP_COMMIT();
    }

    if (pre == 2) { CP_WAIT2(); } else { CP_WAIT1(); }
    __syncthreads();

    uint32_t qf[4][4];
    {
        int arow = w * 16 + (lane & 7) + ((lane & 8) ? 8 : 0);
        int asel = (lane >> 4) & 1;
        #pragma unroll
        for (int ks = 0; ks < 4; ks++) {
            uint32_t off = (uint32_t)(arow * 128 + (ks * 2 + asel) * 16);
            off ^= (off >> 3) & 0x70;
            ldm_x4(qf[ks], base + off);
        }
    }

    float Oa[8][4];
    #pragma unroll
    for (int s = 0; s < 8; s++)
        #pragma unroll
        for (int r = 0; r < 4; r++) Oa[s][r] = 0.f;
    float l0r = 0.f, l1r = 0.f;

    int kRowBase = (lane & 7) + ((lane >= 16) ? 8 : 0);
    int kChkSel  = (lane & 8) ? 1 : 0;
    int vRowBase = (lane & 7) + ((lane & 8) ? 8 : 0);
    int vColB    = ((lane >= 16) ? 16 : 0);

    for (int jt = 0; jt < nt; jt++) {
        if (jt + 1 < nt) { CP_WAIT1(); } else { CP_WAIT0(); }
        __syncthreads();

        // prefetch first (same reordering as the GEMM)
        if (jt + 2 < nt) {
            uint32_t sn = base + AQ_BYTES + ((jt + 2) % 3) * AST_SZ;
            size_t koff = gbase + (size_t)((jt + 2) * 128) * E_;
            cpa_tile128(Kg + koff, E_, 0, sn);
            cpa_tile128(Vg + koff, E_, 0, sn + 16384);
            CP_COMMIT();
        }

        uint32_t sc = base + AQ_BYTES + (jt % 3) * AST_SZ;
        uint32_t sK = sc, sV = sc + 16384;
        bool edge = (jt == nt - 1);

        #pragma unroll
        for (int h2 = 0; h2 < 2; h2++) {
            if (edge && h2 == 1 && w < 4) continue;
            int rowOff = h2 * 64;

            float S[8][4];
            #pragma unroll
            for (int s = 0; s < 8; s++)
                #pragma unroll
                for (int r = 0; r < 4; r++) S[s][r] = 0.f;

            #pragma unroll
            for (int ks = 0; ks < 4; ks++) {
                #pragma unroll
                for (int g = 0; g < 4; g++) {
                    uint32_t k4[4];
                    uint32_t off = (uint32_t)((rowOff + g * 16 + kRowBase) * 128 +
                                              (ks * 2 + kChkSel) * 16);
                    off ^= (off >> 3) & 0x70;
                    ldm_x4(k4, sK + off);
                    mma16816h(S[2 * g],     qf[ks], &k4[0]);
                    mma16816h(S[2 * g + 1], qf[ks], &k4[2]);
                }
            }

            if (edge) {
                int qr0 = q0 + w * 16 + gq;
                int kc0 = jt * 128 + rowOff + 2 * tig;
                #pragma unroll
                for (int s = 0; s < 8; s++) {
                    int kc = kc0 + s * 8;
                    if (kc     > qr0)     S[s][0] = -1e30f;
                    if (kc + 1 > qr0)     S[s][1] = -1e30f;
                    if (kc     > qr0 + 8) S[s][2] = -1e30f;
                    if (kc + 1 > qr0 + 8) S[s][3] = -1e30f;
                }
            }

            uint32_t pa[4][4];
            float ls0 = 0.f, ls1 = 0.f;
            #pragma unroll
            for (int kk = 0; kk < 4; kk++) {
                #pragma unroll
                for (int half_ = 0; half_ < 2; half_++) {
                    float* Sr = S[2 * kk + half_];
                    __half2 e0 = h2exp2(__floats2half2_rn(Sr[0] * CEXP, Sr[1] * CEXP));
                    __half2 e1 = h2exp2(__floats2half2_rn(Sr[2] * CEXP, Sr[3] * CEXP));
                    pa[kk][half_ * 2 + 0] = *reinterpret_cast<uint32_t*>(&e0);
                    pa[kk][half_ * 2 + 1] = *reinterpret_cast<uint32_t*>(&e1);
                    float2 f0 = __half22float2(e0);
                    float2 f1 = __half22float2(e1);
                    ls0 += f0.x + f0.y;
                    ls1 += f1.x + f1.y;
                }
            }
            l0r += ls0;
            l1r += ls1;

            #pragma unroll
            for (int kk = 0; kk < 4; kk++) {
                #pragma unroll
                for (int g = 0; g < 4; g++) {
                    uint32_t v4[4];
                    uint32_t off = (uint32_t)((rowOff + kk * 16 + vRowBase) * 128 +
                                              g * 32 + vColB);
                    off ^= (off >> 3) & 0x70;
                    ldm_x4_t(v4, sV + off);
                    mma16816h(Oa[2 * g],     pa[kk], &v4[0]);
                    mma16816h(Oa[2 * g + 1], pa[kk], &v4[2]);
                }
            }
        }
    }

    l0r += __shfl_xor_sync(0xffffffffu, l0r, 1);
    l0r += __shfl_xor_sync(0xffffffffu, l0r, 2);
    l1r += __shfl_xor_sync(0xffffffffu, l1r, 1);
    l1r += __shfl_xor_sync(0xffffffffu, l1r, 2);

    float inv0 = 1.0f / l0r, inv1 = 1.0f / l1r;
    int row0 = q0 + w * 16 + gq;
    #pragma unroll
    for (int s = 0; s < 8; s++) {
        int col = s * 8 + 2 * tig;
        size_t o0 = gbase + (size_t)row0 * E_ + col;
        size_t o1 = gbase + (size_t)(row0 + 8) * E_ + col;
        *reinterpret_cast<uint32_t*>(O + o0) = pack_h2(Oa[s][0] * inv0, Oa[s][1] * inv0);
        *reinterpret_cast<uint32_t*>(O + o1) = pack_h2(Oa[s][2] * inv1, Oa[s][3] * inv1);
    }
}

// ---------------------------------------------------------------------------
// Launch
// ---------------------------------------------------------------------------
extern "C" void kernel_launch(void* const* d_in, const int* in_sizes, int n_in,
                              void* d_out, int out_size) {
    (void)in_sizes; (void)n_in; (void)out_size;
    const float* x     = (const float*)d_in[0];
    const float* ln1_g = (const float*)d_in[1];
    const float* ln1_b = (const float*)d_in[2];
    const float* Wq    = (const float*)d_in[3];
    const float* bq    = (const float*)d_in[4];
    const float* Wk    = (const float*)d_in[5];
    const float* bk    = (const float*)d_in[6];
    const float* Wv    = (const float*)d_in[7];
    const float* bv    = (const float*)d_in[8];
    const float* Wp    = (const float*)d_in[9];
    const float* bp    = (const float*)d_in[10];
    const float* ln2_g = (const float*)d_in[11];
    const float* ln2_b = (const float*)d_in[12];
    const float* W1    = (const float*)d_in[13];
    const float* b1    = (const float*)d_in[14];
    const float* W2    = (const float*)d_in[15];
    const float* b2    = (const float*)d_in[16];
    float* out = (float*)d_out;

    __half *a, *f, *q, *k, *v, *wq, *wk, *wv, *wp, *w1, *w2;
    cudaGetSymbolAddress((void**)&a, g_a);
    cudaGetSymbolAddress((void**)&f, g_f);
    cudaGetSymbolAddress((void**)&q, g_q);
    cudaGetSymbolAddress((void**)&k, g_k);
    cudaGetSymbolAddress((void**)&v, g_v);
    cudaGetSymbolAddress((void**)&wq, g_wq);
    cudaGetSymbolAddress((void**)&wk, g_wk);
    cudaGetSymbolAddress((void**)&wv, g_wv);
    cudaGetSymbolAddress((void**)&wp, g_wp);
    cudaGetSymbolAddress((void**)&w1, g_w1);
    cudaGetSymbolAddress((void**)&w2, g_w2);

    __half* r1 = q;   // fp16 residual stream (g_q free after attention)

    cudaFuncSetAttribute(attn_mma_kernel,
                         cudaFuncAttributeMaxDynamicSharedMemorySize, ATTN_SMEM);
    cudaFuncSetAttribute(hgemm_kernel<1>,
                         cudaFuncAttributeMaxDynamicSharedMemorySize, HGSMEM);
    cudaFuncSetAttribute(hgemm_kernel<3>,
                         cudaFuncAttributeMaxDynamicSharedMemorySize, HGSMEM);
    cudaFuncSetAttribute(hgemm_kernel<4>,
                         cudaFuncAttributeMaxDynamicSharedMemorySize, HGSMEM);
    cudaFuncSetAttribute(qkv_kernel,
                         cudaFuncAttributeMaxDynamicSharedMemorySize, HGSMEM);

    PrepArgs pa;
    pa.src[0] = Wq; pa.dst[0] = wq; pa.K[0] = E_;   pa.N[0] = E_;   pa.base[0] = 0;    pa.nx[0] = 16;
    pa.src[1] = Wk; pa.dst[1] = wk; pa.K[1] = E_;   pa.N[1] = E_;   pa.base[1] = 256;  pa.nx[1] = 16;
    pa.src[2] = Wv; pa.dst[2] = wv; pa.K[2] = E_;   pa.N[2] = E_;   pa.base[2] = 512;  pa.nx[2] = 16;
    pa.src[3] = Wp; pa.dst[3] = wp; pa.K[3] = E_;   pa.N[3] = E_;   pa.base[3] = 768;  pa.nx[3] = 16;
    pa.src[4] = W1; pa.dst[4] = w1; pa.K[4] = E_;   pa.N[4] = DFF_; pa.base[4] = 1024; pa.nx[4] = 64;
    pa.src[5] = W2; pa.dst[5] = w2; pa.K[5] = DFF_; pa.N[5] = E_;   pa.base[5] = 2048; pa.nx[5] = 16;
    pa.x = x; pa.ln_g = ln1_g; pa.ln_b = ln1_b; pa.ln_o = a;
    prep_kernel<<<WT_BLOCKS + M_, 256>>>(pa);

    // fused QKV
    QKVArgs qa;
    qa.w[0] = wq; qa.bias[0] = bq; qa.o[0] = q;
    qa.w[1] = wk; qa.bias[1] = bk; qa.o[1] = k;
    qa.w[2] = wv; qa.bias[2] = bv; qa.o[2] = v;
    dim3 gQKV(E_ / 128, M_ / 128, 3);
    qkv_kernel<<<gQKV, 256, HGSMEM>>>(a, qa);

    // attention -> a
    dim3 gA(T_ / 128, B_ * H_);
    attn_mma_kernel<<<gA, 256, ATTN_SMEM>>>(q, k, v, a);

    // proj + residual(x fp32) -> r1 (fp16 residual stream)
    dim3 gE(E_ / 128, M_ / 128);
    hgemm_kernel<3><<<gE, 256, HGSMEM>>>(a, wp, bp, x, nullptr, nullptr, r1,
                                         M_, E_, E_);

    // ln2 (fp16 in) -> fp16
    ln_h16_kernel<<<M_, 256>>>(r1, ln2_g, ln2_b, a);

    // FFN1 (relu -> fp16)
    dim3 gF1(DFF_ / 128, M_ / 128);
    hgemm_kernel<1><<<gF1, 256, HGSMEM>>>(a, w1, b1, nullptr, nullptr, nullptr, f,
                                          M_, DFF_, E_);

    // FFN2 + residual(r1 fp16) -> out (fp32)
    hgemm_kernel<4><<<gE, 256, HGSMEM>>>(f, w2, b2, nullptr, r1, out, nullptr,
                                         M_, E_, DFF_);
}

// round 16
// speedup vs baseline: 1.0032x; 1.0032x over previous
#include <cuda_runtime.h>
#include <cuda_fp16.h>
#include <cstdint>

// Problem constants
#define B_   4
#define T_   2048
#define E_   1024
#define H_   16
#define HS_  64
#define DFF_ 4096
#define M_   (B_ * T_)   // 8192 rows

// ---------------------------------------------------------------------------
// Scratch (device globals)
// ---------------------------------------------------------------------------
__device__ __half g_a[(size_t)M_ * E_];     // fp16 activations
__device__ __half g_f[(size_t)M_ * DFF_];   // fp16 FFN hidden
__device__ __half g_q[(size_t)M_ * E_], g_k[(size_t)M_ * E_], g_v[(size_t)M_ * E_];
// fp16 transposed weights [N,K]
__device__ __half g_wq[(size_t)E_ * E_], g_wk[(size_t)E_ * E_];
__device__ __half g_wv[(size_t)E_ * E_], g_wp[(size_t)E_ * E_];
__device__ __half g_w1[(size_t)E_ * DFF_], g_w2[(size_t)DFF_ * E_];

// ---------------------------------------------------------------------------
// Helpers
// ---------------------------------------------------------------------------
__device__ __forceinline__ uint32_t smem_u32(const void* p) {
    uint32_t a;
    asm("{ .reg .u64 t; cvta.to.shared.u64 t, %1; cvt.u32.u64 %0, t; }"
        : "=r"(a) : "l"(p));
    return a;
}

__device__ __forceinline__ void ldm_x4(uint32_t* r, uint32_t addr) {
    asm volatile("ldmatrix.sync.aligned.m8n8.x4.shared.b16 {%0,%1,%2,%3}, [%4];"
                 : "=r"(r[0]), "=r"(r[1]), "=r"(r[2]), "=r"(r[3]) : "r"(addr));
}
__device__ __forceinline__ void ldm_x4_t(uint32_t* r, uint32_t addr) {
    asm volatile("ldmatrix.sync.aligned.m8n8.x4.trans.shared.b16 {%0,%1,%2,%3}, [%4];"
                 : "=r"(r[0]), "=r"(r[1]), "=r"(r[2]), "=r"(r[3]) : "r"(addr));
}

__device__ __forceinline__ void mma16816h(float* c, const uint32_t* a, const uint32_t* b) {
    asm volatile(
        "mma.sync.aligned.m16n8k16.row.col.f32.f16.f16.f32 "
        "{%0,%1,%2,%3}, {%4,%5,%6,%7}, {%8,%9}, {%0,%1,%2,%3};"
        : "+f"(c[0]), "+f"(c[1]), "+f"(c[2]), "+f"(c[3])
        : "r"(a[0]), "r"(a[1]), "r"(a[2]), "r"(a[3]), "r"(b[0]), "r"(b[1]));
}

#define CP_ASYNC16(dst, src) \
    asm volatile("cp.async.cg.shared.global [%0], [%1], 16;" :: "r"(dst), "l"(src))
#define CP_COMMIT() asm volatile("cp.async.commit_group;" ::: "memory")
#define CP_WAIT0() asm volatile("cp.async.wait_group 0;" ::: "memory")
#define CP_WAIT1() asm volatile("cp.async.wait_group 1;" ::: "memory")
#define CP_WAIT2() asm volatile("cp.async.wait_group 2;" ::: "memory")

__device__ __forceinline__ uint32_t pack_h2(float a, float b) {
    __half2 h = __floats2half2_rn(a, b);
    return *reinterpret_cast<uint32_t*>(&h);
}

// 128-row x 128-byte K-major tile, SW128 swizzle, 256 threads
__device__ __forceinline__ void cpa_tile128(const __half* __restrict__ g,
                                            int ldk, int k0, uint32_t sbase) {
    int tid = threadIdx.x;
    #pragma unroll
    for (int i = 0; i < 4; i++) {
        int idx = i * 256 + tid;
        int r = idx >> 3, c = idx & 7;
        uint32_t off = (uint32_t)(r * 128 + c * 16);
        off ^= (off >> 3) & 0x70;
        CP_ASYNC16(sbase + off, g + (size_t)r * ldk + k0 + c * 8);
    }
}

// ---------------------------------------------------------------------------
// LN body (shared)
// ---------------------------------------------------------------------------
__device__ __forceinline__ void ln_body(float vx, float vy, float vz, float vw,
                                        const float* __restrict__ gamma,
                                        const float* __restrict__ beta,
                                        __half* __restrict__ O, int row, int t,
                                        float* red) {
    float s1 = vx + vy + vz + vw;
    float s2 = vx * vx + vy * vy + vz * vz + vw * vw;
    #pragma unroll
    for (int o = 16; o > 0; o >>= 1) {
        s1 += __shfl_xor_sync(0xffffffffu, s1, o);
        s2 += __shfl_xor_sync(0xffffffffu, s2, o);
    }
    int lane = t & 31, w = t >> 5;
    if (lane == 0) { red[w] = s1; red[w + 32] = s2; }
    __syncthreads();
    float ts1 = 0.f, ts2 = 0.f;
    #pragma unroll
    for (int i = 0; i < 8; i++) { ts1 += red[i]; ts2 += red[i + 32]; }

    float mu  = ts1 * (1.0f / E_);
    float var = ts2 * (1.0f / E_) - mu * mu;
    float rs  = rsqrtf(var + 1e-5f);

    float4 g4 = ((const float4*)gamma)[t];
    float4 b4 = ((const float4*)beta)[t];
    float o0 = (vx - mu) * rs * g4.x + b4.x;
    float o1 = (vy - mu) * rs * g4.y + b4.y;
    float o2 = (vz - mu) * rs * g4.z + b4.z;
    float o3 = (vw - mu) * rs * g4.w + b4.w;

    size_t idx = (size_t)row * E_ + t * 4;
    *reinterpret_cast<uint2*>(O + idx) = make_uint2(pack_h2(o0, o1), pack_h2(o2, o3));
}

// ---------------------------------------------------------------------------
// Fused prep: blocks [0,3072) = weight transpose+convert; [3072,..) = ln1.
// ---------------------------------------------------------------------------
struct PrepArgs {
    const float* src[6];
    __half* dst[6];
    int K[6], N[6];
    int base[6];
    int nx[6];
    const float* x;
    const float* ln_g;
    const float* ln_b;
    __half* ln_o;
};

#define WT_BLOCKS 3072

__global__ __launch_bounds__(256)
void prep_kernel(PrepArgs a) {
    __shared__ float t[64][65];
    int bid = blockIdx.x;
    int tid = threadIdx.x;

    if (bid >= WT_BLOCKS) {
        int row = bid - WT_BLOCKS;
        float4 v = ((const float4*)(a.x + (size_t)row * E_))[tid];
        ln_body(v.x, v.y, v.z, v.w, a.ln_g, a.ln_b, a.ln_o, row, tid, &t[0][0]);
        return;
    }

    int z = 0;
    #pragma unroll
    for (int i = 1; i < 6; i++)
        if (bid >= a.base[i]) z = i;
    int local = bid - a.base[z];
    int bx = local % a.nx[z];
    int by = local / a.nx[z];
    const float* W = a.src[z];
    __half* T = a.dst[z];
    int K = a.K[z], N = a.N[z];
    int n0 = bx * 64, k0 = by * 64;

    int r = tid >> 2, c0 = (tid & 3) * 16;
    const float4* src = reinterpret_cast<const float4*>(
        W + (size_t)(k0 + r) * N + n0 + c0);
    #pragma unroll
    for (int j = 0; j < 4; j++) {
        float4 v = src[j];
        t[r][c0 + j * 4 + 0] = v.x;
        t[r][c0 + j * 4 + 1] = v.y;
        t[r][c0 + j * 4 + 2] = v.z;
        t[r][c0 + j * 4 + 3] = v.w;
    }
    __syncthreads();

    int nr = tid >> 2;
    uint32_t o8[8];
    #pragma unroll
    for (int j = 0; j < 8; j++)
        o8[j] = pack_h2(t[c0 + 2 * j][nr], t[c0 + 2 * j + 1][nr]);
    __half* dst = T + (size_t)(n0 + nr) * K + k0 + c0;
    *reinterpret_cast<uint4*>(dst)     = make_uint4(o8[0], o8[1], o8[2], o8[3]);
    *reinterpret_cast<uint4*>(dst + 8) = make_uint4(o8[4], o8[5], o8[6], o8[7]);
}

// ---------------------------------------------------------------------------
// LayerNorm fp16-in -> fp16 (residual stream)
// ---------------------------------------------------------------------------
__global__ __launch_bounds__(256)
void ln_h16_kernel(const __half* __restrict__ in, const float* __restrict__ gamma,
                   const float* __restrict__ beta, __half* __restrict__ O) {
    __shared__ float red[64];
    int row = blockIdx.x;
    int t = threadIdx.x;
    uint2 pv = ((const uint2*)(in + (size_t)row * E_))[t];
    float2 f01 = __half22float2(*reinterpret_cast<__half2*>(&pv.x));
    float2 f23 = __half22float2(*reinterpret_cast<__half2*>(&pv.y));
    ln_body(f01.x, f01.y, f23.x, f23.y, gamma, beta, O, row, t, red);
}

// ---------------------------------------------------------------------------
// fp16 GEMM: C[M,N] = A[M,K] @ Wt[N,K]^T + bias (+...)
// 128x128 CTA, BK=64, 8 warps, 3-stage cp.async, 2 CTAs/SM.
// Prefetch INTERLEAVED into compute: A-tile after ks=0's MMAs, B-tile +
// commit after ks=1's MMAs (compute starts immediately at iter top; LSU
// issue diluted across the ks loop). Stage safety identical to R14.
// EPI: 0 bias->fp16 ; 1 bias+relu->fp16 ; 3 bias+res(fp32)->fp16 ;
//      4 bias+res(fp16)->fp32
// ---------------------------------------------------------------------------
#define HTILE_B  16384
#define HSTAGE_B (2 * HTILE_B)
#define HGSMEM   (3 * HSTAGE_B + 128)

template<int EPI>
__device__ __forceinline__ void gemm_core_h(
        const __half* __restrict__ A, const __half* __restrict__ Bw,
        const float* __restrict__ bias, const float* __restrict__ resf,
        const __half* __restrict__ res16,
        float* __restrict__ Cf, __half* __restrict__ Hh,
        int M, int N, int K, int m0, int n0, uint32_t base) {
    int tid = threadIdx.x, lane = tid & 31, wid = tid >> 5;
    int warp_m = wid >> 2;
    int warp_n = wid & 3;

    const __half* Ab = A  + (size_t)m0 * K;
    const __half* Bb = Bw + (size_t)n0 * K;

    int amat = lane >> 3, arin = lane & 7;
    int aRow = warp_m * 64 + (amat & 1) * 8 + arin;
    int aChk = amat >> 1;
    int bRow4 = warp_n * 32 + ((lane >> 4) & 1) * 8 + (lane & 7);
    int bChk4 = (lane >> 3) & 1;

    float C[4][4][4];
    #pragma unroll
    for (int i = 0; i < 4; i++)
        #pragma unroll
        for (int j = 0; j < 4; j++)
            #pragma unroll
            for (int r = 0; r < 4; r++) C[i][j][r] = 0.f;

    int NT = K >> 6;

    cpa_tile128(Ab, K, 0, base);
    cpa_tile128(Bb, K, 0, base + HTILE_B);
    CP_COMMIT();
    cpa_tile128(Ab, K, 64, base + HSTAGE_B);
    cpa_tile128(Bb, K, 64, base + HSTAGE_B + HTILE_B);
    CP_COMMIT();

    for (int kt = 0; kt < NT; kt++) {
        if (kt + 1 < NT) { CP_WAIT1(); } else { CP_WAIT0(); }
        __syncthreads();

        uint32_t sc = base + (kt % 3) * HSTAGE_B;
        uint32_t sA = sc, sB = sc + HTILE_B;
        bool pf = (kt + 2 < NT);
        uint32_t sn = base + ((kt + 2) % 3) * HSTAGE_B;
        int kpf = (kt + 2) << 6;

        #pragma unroll
        for (int ks = 0; ks < 4; ks++) {
            uint32_t a4[4][4], b4[2][4];
            #pragma unroll
            for (int mi = 0; mi < 4; mi++) {
                uint32_t off = (uint32_t)((aRow + mi * 16) * 128 + (aChk + ks * 2) * 16);
                off ^= (off >> 3) & 0x70;
                ldm_x4(a4[mi], sA + off);
            }
            #pragma unroll
            for (int ni2 = 0; ni2 < 2; ni2++) {
                uint32_t off = (uint32_t)((bRow4 + ni2 * 16) * 128 + (bChk4 + ks * 2) * 16);
                off ^= (off >> 3) & 0x70;
                ldm_x4(b4[ni2], sB + off);
            }
            #pragma unroll
            for (int mi = 0; mi < 4; mi++) {
                #pragma unroll
                for (int ni2 = 0; ni2 < 2; ni2++) {
                    mma16816h(C[mi][2 * ni2],     a4[mi], &b4[ni2][0]);
                    mma16816h(C[mi][2 * ni2 + 1], a4[mi], &b4[ni2][2]);
                }
            }
            // interleaved prefetch: A after ks=0, B + commit after ks=1
            if (ks == 0 && pf) cpa_tile128(Ab, K, kpf, sn);
            if (ks == 1 && pf) { cpa_tile128(Bb, K, kpf, sn + HTILE_B); CP_COMMIT(); }
        }
    }

    int gq = lane >> 2, tig = lane & 3;
    #pragma unroll
    for (int mi = 0; mi < 4; mi++) {
        #pragma unroll
        for (int ni = 0; ni < 4; ni++) {
            int m = m0 + warp_m * 64 + mi * 16 + gq;
            int n = n0 + warp_n * 32 + ni * 8 + tig * 2;
            float2 bv = *reinterpret_cast<const float2*>(&bias[n]);
            #pragma unroll
            for (int half_ = 0; half_ < 2; half_++) {
                int row = m + half_ * 8;
                float a0 = C[mi][ni][half_ * 2 + 0] + bv.x;
                float a1 = C[mi][ni][half_ * 2 + 1] + bv.y;
                size_t o = (size_t)row * N + n;
                if (EPI == 0) {
                    *reinterpret_cast<uint32_t*>(Hh + o) = pack_h2(a0, a1);
                } else if (EPI == 1) {
                    a0 = fmaxf(a0, 0.f); a1 = fmaxf(a1, 0.f);
                    *reinterpret_cast<uint32_t*>(Hh + o) = pack_h2(a0, a1);
                } else if (EPI == 3) {
                    float2 rv = *reinterpret_cast<const float2*>(&resf[o]);
                    a0 += rv.x; a1 += rv.y;
                    *reinterpret_cast<uint32_t*>(Hh + o) = pack_h2(a0, a1);
                } else {  // EPI == 4
                    uint32_t rp = *reinterpret_cast<const uint32_t*>(&res16[o]);
                    float2 rv = __half22float2(*reinterpret_cast<__half2*>(&rp));
                    a0 += rv.x; a1 += rv.y;
                    *reinterpret_cast<float2*>(&Cf[o]) = make_float2(a0, a1);
                }
            }
        }
    }
}

template<int EPI>
__global__ __launch_bounds__(256, 2)
void hgemm_kernel(const __half* __restrict__ A, const __half* __restrict__ Bw,
                  const float* __restrict__ bias, const float* __restrict__ resf,
                  const __half* __restrict__ res16,
                  float* __restrict__ Cf, __half* __restrict__ Hh,
                  int M, int N, int K) {
    extern __shared__ char dsm[];
    uint32_t base = smem_u32(dsm);
    base = (base + 127) & ~127u;
    gemm_core_h<EPI>(A, Bw, bias, resf, res16, Cf, Hh, M, N, K,
                     blockIdx.y * 128, blockIdx.x * 128, base);
}

struct QKVArgs {
    const __half* w[3];
    const float* bias[3];
    __half* o[3];
};

__global__ __launch_bounds__(256, 2)
void qkv_kernel(const __half* __restrict__ A, QKVArgs args) {
    extern __shared__ char dsm[];
    uint32_t base = smem_u32(dsm);
    base = (base + 127) & ~127u;
    int z = blockIdx.z;
    gemm_core_h<0>(A, args.w[z], args.bias[z], nullptr, nullptr, nullptr,
                   args.o[z], M_, E_, E_,
                   blockIdx.y * 128, blockIdx.x * 128, base);
}

// ---------------------------------------------------------------------------
// fp16 tensor-core causal flash attention (exact R14 config:
// 128-key tiles as two halves, prefetch AFTER compute, 3-stage, 2 CTA/SM)
// ---------------------------------------------------------------------------
#define AQ_BYTES  16384
#define AST_SZ    32768
#define ATTN_SMEM (AQ_BYTES + 3 * AST_SZ + 128)
#define CEXP 0.18033688011112042f  // 0.125 * log2(e)

__global__ __launch_bounds__(256, 2)
void attn_mma_kernel(const __half* __restrict__ Qg, const __half* __restrict__ Kg,
                     const __half* __restrict__ Vg, __half* __restrict__ O) {
    extern __shared__ char dsm[];
    uint32_t base = smem_u32(dsm);
    base = (base + 127) & ~127u;

    int tid = threadIdx.x, lane = tid & 31, w = tid >> 5;
    int gq = lane >> 2, tig = lane & 3;
    int qi = gridDim.x - 1 - blockIdx.x;
    int q0 = qi * 128;
    int bh = blockIdx.y;
    int b = bh >> 4, h = bh & 15;
    size_t gbase = ((size_t)b * T_) * E_ + (size_t)h * HS_;

    int nt = (q0 >> 7) + 1;

    cpa_tile128(Qg + gbase + (size_t)q0 * E_, E_, 0, base);
    CP_COMMIT();
    int pre = nt < 2 ? nt : 2;
    for (int st = 0; st < pre; st++) {
        uint32_t s = base + AQ_BYTES + st * AST_SZ;
        size_t koff = gbase + (size_t)(st * 128) * E_;
        cpa_tile128(Kg + koff, E_, 0, s);
        cpa_tile128(Vg + koff, E_, 0, s + 16384);
        CP_COMMIT();
    }

    if (pre == 2) { CP_WAIT2(); } else { CP_WAIT1(); }
    __syncthreads();

    uint32_t qf[4][4];
    {
        int arow = w * 16 + (lane & 7) + ((lane & 8) ? 8 : 0);
        int asel = (lane >> 4) & 1;
        #pragma unroll
        for (int ks = 0; ks < 4; ks++) {
            uint32_t off = (uint32_t)(arow * 128 + (ks * 2 + asel) * 16);
            off ^= (off >> 3) & 0x70;
            ldm_x4(qf[ks], base + off);
        }
    }

    float Oa[8][4];
    #pragma unroll
    for (int s = 0; s < 8; s++)
        #pragma unroll
        for (int r = 0; r < 4; r++) Oa[s][r] = 0.f;
    float l0r = 0.f, l1r = 0.f;

    int kRowBase = (lane & 7) + ((lane >= 16) ? 8 : 0);
    int kChkSel  = (lane & 8) ? 1 : 0;
    int vRowBase = (lane & 7) + ((lane & 8) ? 8 : 0);
    int vColB    = ((lane >= 16) ? 16 : 0);

    for (int jt = 0; jt < nt; jt++) {
        if (jt + 1 < nt) { CP_WAIT1(); } else { CP_WAIT0(); }
        __syncthreads();

        uint32_t sc = base + AQ_BYTES + (jt % 3) * AST_SZ;
        uint32_t sK = sc, sV = sc + 16384;
        bool edge = (jt == nt - 1);

        #pragma unroll
        for (int h2 = 0; h2 < 2; h2++) {
            if (edge && h2 == 1 && w < 4) continue;
            int rowOff = h2 * 64;

            float S[8][4];
            #pragma unroll
            for (int s = 0; s < 8; s++)
                #pragma unroll
                for (int r = 0; r < 4; r++) S[s][r] = 0.f;

            #pragma unroll
            for (int ks = 0; ks < 4; ks++) {
                #pragma unroll
                for (int g = 0; g < 4; g++) {
                    uint32_t k4[4];
                    uint32_t off = (uint32_t)((rowOff + g * 16 + kRowBase) * 128 +
                                              (ks * 2 + kChkSel) * 16);
                    off ^= (off >> 3) & 0x70;
                    ldm_x4(k4, sK + off);
                    mma16816h(S[2 * g],     qf[ks], &k4[0]);
                    mma16816h(S[2 * g + 1], qf[ks], &k4[2]);
                }
            }

            if (edge) {
                int qr0 = q0 + w * 16 + gq;
                int kc0 = jt * 128 + rowOff + 2 * tig;
                #pragma unroll
                for (int s = 0; s < 8; s++) {
                    int kc = kc0 + s * 8;
                    if (kc     > qr0)     S[s][0] = -1e30f;
                    if (kc + 1 > qr0)     S[s][1] = -1e30f;
                    if (kc     > qr0 + 8) S[s][2] = -1e30f;
                    if (kc + 1 > qr0 + 8) S[s][3] = -1e30f;
                }
            }

            uint32_t pa[4][4];
            float ls0 = 0.f, ls1 = 0.f;
            #pragma unroll
            for (int kk = 0; kk < 4; kk++) {
                #pragma unroll
                for (int half_ = 0; half_ < 2; half_++) {
                    float* Sr = S[2 * kk + half_];
                    __half2 e0 = h2exp2(__floats2half2_rn(Sr[0] * CEXP, Sr[1] * CEXP));
                    __half2 e1 = h2exp2(__floats2half2_rn(Sr[2] * CEXP, Sr[3] * CEXP));
                    pa[kk][half_ * 2 + 0] = *reinterpret_cast<uint32_t*>(&e0);
                    pa[kk][half_ * 2 + 1] = *reinterpret_cast<uint32_t*>(&e1);
                    float2 f0 = __half22float2(e0);
                    float2 f1 = __half22float2(e1);
                    ls0 += f0.x + f0.y;
                    ls1 += f1.x + f1.y;
                }
            }
            l0r += ls0;
            l1r += ls1;

            #pragma unroll
            for (int kk = 0; kk < 4; kk++) {
                #pragma unroll
                for (int g = 0; g < 4; g++) {
                    uint32_t v4[4];
                    uint32_t off = (uint32_t)((rowOff + kk * 16 + vRowBase) * 128 +
                                              g * 32 + vColB);
                    off ^= (off >> 3) & 0x70;
                    ldm_x4_t(v4, sV + off);
                    mma16816h(Oa[2 * g],     pa[kk], &v4[0]);
                    mma16816h(Oa[2 * g + 1], pa[kk], &v4[2]);
                }
            }
        }

        // prefetch AFTER compute (R14 ordering — measured best)
        if (jt + 2 < nt) {
            uint32_t sn = base + AQ_BYTES + ((jt + 2) % 3) * AST_SZ;
            size_t koff = gbase + (size_t)((jt + 2) * 128) * E_;
            cpa_tile128(Kg + koff, E_, 0, sn);
            cpa_tile128(Vg + koff, E_, 0, sn + 16384);
            CP_COMMIT();
        }
    }

    l0r += __shfl_xor_sync(0xffffffffu, l0r, 1);
    l0r += __shfl_xor_sync(0xffffffffu, l0r, 2);
    l1r += __shfl_xor_sync(0xffffffffu, l1r, 1);
    l1r += __shfl_xor_sync(0xffffffffu, l1r, 2);

    float inv0 = 1.0f / l0r, inv1 = 1.0f / l1r;
    int row0 = q0 + w * 16 + gq;
    #pragma unroll
    for (int s = 0; s < 8; s++) {
        int col = s * 8 + 2 * tig;
        size_t o0 = gbase + (size_t)row0 * E_ + col;
        size_t o1 = gbase + (size_t)(row0 + 8) * E_ + col;
        *reinterpret_cast<uint32_t*>(O + o0) = pack_h2(Oa[s][0] * inv0, Oa[s][1] * inv0);
        *reinterpret_cast<uint32_t*>(O + o1) = pack_h2(Oa[s][2] * inv1, Oa[s][3] * inv1);
    }
}

// ---------------------------------------------------------------------------
// Launch
// ---------------------------------------------------------------------------
extern "C" void kernel_launch(void* const* d_in, const int* in_sizes, int n_in,
                              void* d_out, int out_size) {
    (void)in_sizes; (void)n_in; (void)out_size;
    const float* x     = (const float*)d_in[0];
    const float* ln1_g = (const float*)d_in[1];
    const float* ln1_b = (const float*)d_in[2];
    const float* Wq    = (const float*)d_in[3];
    const float* bq    = (const float*)d_in[4];
    const float* Wk    = (const float*)d_in[5];
    const float* bk    = (const float*)d_in[6];
    const float* Wv    = (const float*)d_in[7];
    const float* bv    = (const float*)d_in[8];
    const float* Wp    = (const float*)d_in[9];
    const float* bp    = (const float*)d_in[10];
    const float* ln2_g = (const float*)d_in[11];
    const float* ln2_b = (const float*)d_in[12];
    const float* W1    = (const float*)d_in[13];
    const float* b1    = (const float*)d_in[14];
    const float* W2    = (const float*)d_in[15];
    const float* b2    = (const float*)d_in[16];
    float* out = (float*)d_out;

    __half *a, *f, *q, *k, *v, *wq, *wk, *wv, *wp, *w1, *w2;
    cudaGetSymbolAddress((void**)&a, g_a);
    cudaGetSymbolAddress((void**)&f, g_f);
    cudaGetSymbolAddress((void**)&q, g_q);
    cudaGetSymbolAddress((void**)&k, g_k);
    cudaGetSymbolAddress((void**)&v, g_v);
    cudaGetSymbolAddress((void**)&wq, g_wq);
    cudaGetSymbolAddress((void**)&wk, g_wk);
    cudaGetSymbolAddress((void**)&wv, g_wv);
    cudaGetSymbolAddress((void**)&wp, g_wp);
    cudaGetSymbolAddress((void**)&w1, g_w1);
    cudaGetSymbolAddress((void**)&w2, g_w2);

    __half* r1 = q;   // fp16 residual stream (g_q free after attention)

    cudaFuncSetAttribute(attn_mma_kernel,
                         cudaFuncAttributeMaxDynamicSharedMemorySize, ATTN_SMEM);
    cudaFuncSetAttribute(hgemm_kernel<1>,
                         cudaFuncAttributeMaxDynamicSharedMemorySize, HGSMEM);
    cudaFuncSetAttribute(hgemm_kernel<3>,
                         cudaFuncAttributeMaxDynamicSharedMemorySize, HGSMEM);
    cudaFuncSetAttribute(hgemm_kernel<4>,
                         cudaFuncAttributeMaxDynamicSharedMemorySize, HGSMEM);
    cudaFuncSetAttribute(qkv_kernel,
                         cudaFuncAttributeMaxDynamicSharedMemorySize, HGSMEM);

    PrepArgs pa;
    pa.src[0] = Wq; pa.dst[0] = wq; pa.K[0] = E_;   pa.N[0] = E_;   pa.base[0] = 0;    pa.nx[0] = 16;
    pa.src[1] = Wk; pa.dst[1] = wk; pa.K[1] = E_;   pa.N[1] = E_;   pa.base[1] = 256;  pa.nx[1] = 16;
    pa.src[2] = Wv; pa.dst[2] = wv; pa.K[2] = E_;   pa.N[2] = E_;   pa.base[2] = 512;  pa.nx[2] = 16;
    pa.src[3] = Wp; pa.dst[3] = wp; pa.K[3] = E_;   pa.N[3] = E_;   pa.base[3] = 768;  pa.nx[3] = 16;
    pa.src[4] = W1; pa.dst[4] = w1; pa.K[4] = E_;   pa.N[4] = DFF_; pa.base[4] = 1024; pa.nx[4] = 64;
    pa.src[5] = W2; pa.dst[5] = w2; pa.K[5] = DFF_; pa.N[5] = E_;   pa.base[5] = 2048; pa.nx[5] = 16;
    pa.x = x; pa.ln_g = ln1_g; pa.ln_b = ln1_b; pa.ln_o = a;
    prep_kernel<<<WT_BLOCKS + M_, 256>>>(pa);

    // fused QKV
    QKVArgs qa;
    qa.w[0] = wq; qa.bias[0] = bq; qa.o[0] = q;
    qa.w[1] = wk; qa.bias[1] = bk; qa.o[1] = k;
    qa.w[2] = wv; qa.bias[2] = bv; qa.o[2] = v;
    dim3 gQKV(E_ / 128, M_ / 128, 3);
    qkv_kernel<<<gQKV, 256, HGSMEM>>>(a, qa);

    // attention -> a
    dim3 gA(T_ / 128, B_ * H_);
    attn_mma_kernel<<<gA, 256, ATTN_SMEM>>>(q, k, v, a);

    // proj + residual(x fp32) -> r1 (fp16 residual stream)
    dim3 gE(E_ / 128, M_ / 128);
    hgemm_kernel<3><<<gE, 256, HGSMEM>>>(a, wp, bp, x, nullptr, nullptr, r1,
                                         M_, E_, E_);

    // ln2 (fp16 in) -> fp16
    ln_h16_kernel<<<M_, 256>>>(r1, ln2_g, ln2_b, a);

    // FFN1 (relu -> fp16)
    dim3 gF1(DFF_ / 128, M_ / 128);
    hgemm_kernel<1><<<gF1, 256, HGSMEM>>>(a, w1, b1, nullptr, nullptr, nullptr, f,
                                          M_, DFF_, E_);

    // FFN2 + residual(r1 fp16) -> out (fp32)
    hgemm_kernel<4><<<gE, 256, HGSMEM>>>(f, w2, b2, nullptr, r1, out, nullptr,
                                         M_, E_, DFF_);
}

// round 17
// speedup vs baseline: 1.0186x; 1.0153x over previous
#include <cuda_runtime.h>
#include <cuda_fp16.h>
#include <cstdint>

// Problem constants
#define B_   4
#define T_   2048
#define E_   1024
#define H_   16
#define HS_  64
#define DFF_ 4096
#define M_   (B_ * T_)   // 8192 rows

// ---------------------------------------------------------------------------
// Scratch (device globals)
// ---------------------------------------------------------------------------
__device__ __half g_a[(size_t)M_ * E_];     // fp16 activations
__device__ __half g_f[(size_t)M_ * DFF_];   // fp16 FFN hidden
__device__ __half g_q[(size_t)M_ * E_], g_k[(size_t)M_ * E_], g_v[(size_t)M_ * E_];
// fp16 transposed weights [N,K]
__device__ __half g_wq[(size_t)E_ * E_], g_wk[(size_t)E_ * E_];
__device__ __half g_wv[(size_t)E_ * E_], g_wp[(size_t)E_ * E_];
__device__ __half g_w1[(size_t)E_ * DFF_], g_w2[(size_t)DFF_ * E_];

// ---------------------------------------------------------------------------
// Helpers
// ---------------------------------------------------------------------------
__device__ __forceinline__ uint32_t smem_u32(const void* p) {
    uint32_t a;
    asm("{ .reg .u64 t; cvta.to.shared.u64 t, %1; cvt.u32.u64 %0, t; }"
        : "=r"(a) : "l"(p));
    return a;
}

__device__ __forceinline__ void ldm_x4(uint32_t* r, uint32_t addr) {
    asm volatile("ldmatrix.sync.aligned.m8n8.x4.shared.b16 {%0,%1,%2,%3}, [%4];"
                 : "=r"(r[0]), "=r"(r[1]), "=r"(r[2]), "=r"(r[3]) : "r"(addr));
}
__device__ __forceinline__ void ldm_x4_t(uint32_t* r, uint32_t addr) {
    asm volatile("ldmatrix.sync.aligned.m8n8.x4.trans.shared.b16 {%0,%1,%2,%3}, [%4];"
                 : "=r"(r[0]), "=r"(r[1]), "=r"(r[2]), "=r"(r[3]) : "r"(addr));
}

__device__ __forceinline__ void mma16816h(float* c, const uint32_t* a, const uint32_t* b) {
    asm volatile(
        "mma.sync.aligned.m16n8k16.row.col.f32.f16.f16.f32 "
        "{%0,%1,%2,%3}, {%4,%5,%6,%7}, {%8,%9}, {%0,%1,%2,%3};"
        : "+f"(c[0]), "+f"(c[1]), "+f"(c[2]), "+f"(c[3])
        : "r"(a[0]), "r"(a[1]), "r"(a[2]), "r"(a[3]), "r"(b[0]), "r"(b[1]));
}

#define CP_ASYNC16(dst, src) \
    asm volatile("cp.async.cg.shared.global [%0], [%1], 16;" :: "r"(dst), "l"(src))
#define CP_COMMIT() asm volatile("cp.async.commit_group;" ::: "memory")
#define CP_WAIT0() asm volatile("cp.async.wait_group 0;" ::: "memory")
#define CP_WAIT1() asm volatile("cp.async.wait_group 1;" ::: "memory")
#define CP_WAIT2() asm volatile("cp.async.wait_group 2;" ::: "memory")

__device__ __forceinline__ uint32_t pack_h2(float a, float b) {
    __half2 h = __floats2half2_rn(a, b);
    return *reinterpret_cast<uint32_t*>(&h);
}

// 128-row x 128-byte K-major tile, SW128 swizzle, 256 threads
__device__ __forceinline__ void cpa_tile128(const __half* __restrict__ g,
                                            int ldk, int k0, uint32_t sbase) {
    int tid = threadIdx.x;
    #pragma unroll
    for (int i = 0; i < 4; i++) {
        int idx = i * 256 + tid;
        int r = idx >> 3, c = idx & 7;
        uint32_t off = (uint32_t)(r * 128 + c * 16);
        off ^= (off >> 3) & 0x70;
        CP_ASYNC16(sbase + off, g + (size_t)r * ldk + k0 + c * 8);
    }
}

// ---------------------------------------------------------------------------
// LN body (shared by prep kernel and fp16-in LN)
// ---------------------------------------------------------------------------
__device__ __forceinline__ void ln_body(float vx, float vy, float vz, float vw,
                                        const float* __restrict__ gamma,
                                        const float* __restrict__ beta,
                                        __half* __restrict__ O, int row, int t,
                                        float* red) {
    float s1 = vx + vy + vz + vw;
    float s2 = vx * vx + vy * vy + vz * vz + vw * vw;
    #pragma unroll
    for (int o = 16; o > 0; o >>= 1) {
        s1 += __shfl_xor_sync(0xffffffffu, s1, o);
        s2 += __shfl_xor_sync(0xffffffffu, s2, o);
    }
    int lane = t & 31, w = t >> 5;
    if (lane == 0) { red[w] = s1; red[w + 32] = s2; }
    __syncthreads();
    float ts1 = 0.f, ts2 = 0.f;
    #pragma unroll
    for (int i = 0; i < 8; i++) { ts1 += red[i]; ts2 += red[i + 32]; }

    float mu  = ts1 * (1.0f / E_);
    float var = ts2 * (1.0f / E_) - mu * mu;
    float rs  = rsqrtf(var + 1e-5f);

    float4 g4 = ((const float4*)gamma)[t];
    float4 b4 = ((const float4*)beta)[t];
    float o0 = (vx - mu) * rs * g4.x + b4.x;
    float o1 = (vy - mu) * rs * g4.y + b4.y;
    float o2 = (vz - mu) * rs * g4.z + b4.z;
    float o3 = (vw - mu) * rs * g4.w + b4.w;

    size_t idx = (size_t)row * E_ + t * 4;
    *reinterpret_cast<uint2*>(O + idx) = make_uint2(pack_h2(o0, o1), pack_h2(o2, o3));
}

// ---------------------------------------------------------------------------
// Fused prep: blocks [0,3072) = weight transpose+convert; [3072,..) = ln1.
// ---------------------------------------------------------------------------
struct PrepArgs {
    const float* src[6];
    __half* dst[6];
    int K[6], N[6];
    int base[6];
    int nx[6];
    const float* x;
    const float* ln_g;
    const float* ln_b;
    __half* ln_o;
};

#define WT_BLOCKS 3072

__global__ __launch_bounds__(256)
void prep_kernel(PrepArgs a) {
    __shared__ float t[64][65];
    int bid = blockIdx.x;
    int tid = threadIdx.x;

    if (bid >= WT_BLOCKS) {
        int row = bid - WT_BLOCKS;
        float4 v = ((const float4*)(a.x + (size_t)row * E_))[tid];
        ln_body(v.x, v.y, v.z, v.w, a.ln_g, a.ln_b, a.ln_o, row, tid, &t[0][0]);
        return;
    }

    int z = 0;
    #pragma unroll
    for (int i = 1; i < 6; i++)
        if (bid >= a.base[i]) z = i;
    int local = bid - a.base[z];
    int bx = local % a.nx[z];
    int by = local / a.nx[z];
    const float* W = a.src[z];
    __half* T = a.dst[z];
    int K = a.K[z], N = a.N[z];
    int n0 = bx * 64, k0 = by * 64;

    int r = tid >> 2, c0 = (tid & 3) * 16;
    const float4* src = reinterpret_cast<const float4*>(
        W + (size_t)(k0 + r) * N + n0 + c0);
    #pragma unroll
    for (int j = 0; j < 4; j++) {
        float4 v = src[j];
        t[r][c0 + j * 4 + 0] = v.x;
        t[r][c0 + j * 4 + 1] = v.y;
        t[r][c0 + j * 4 + 2] = v.z;
        t[r][c0 + j * 4 + 3] = v.w;
    }
    __syncthreads();

    int nr = tid >> 2;
    uint32_t o8[8];
    #pragma unroll
    for (int j = 0; j < 8; j++)
        o8[j] = pack_h2(t[c0 + 2 * j][nr], t[c0 + 2 * j + 1][nr]);
    __half* dst = T + (size_t)(n0 + nr) * K + k0 + c0;
    *reinterpret_cast<uint4*>(dst)     = make_uint4(o8[0], o8[1], o8[2], o8[3]);
    *reinterpret_cast<uint4*>(dst + 8) = make_uint4(o8[4], o8[5], o8[6], o8[7]);
}

// ---------------------------------------------------------------------------
// LayerNorm fp16-in -> fp16 (residual stream)
// ---------------------------------------------------------------------------
__global__ __launch_bounds__(256)
void ln_h16_kernel(const __half* __restrict__ in, const float* __restrict__ gamma,
                   const float* __restrict__ beta, __half* __restrict__ O) {
    __shared__ float red[64];
    int row = blockIdx.x;
    int t = threadIdx.x;
    uint2 pv = ((const uint2*)(in + (size_t)row * E_))[t];
    float2 f01 = __half22float2(*reinterpret_cast<__half2*>(&pv.x));
    float2 f23 = __half22float2(*reinterpret_cast<__half2*>(&pv.y));
    ln_body(f01.x, f01.y, f23.x, f23.y, gamma, beta, O, row, t, red);
}

// ---------------------------------------------------------------------------
// fp16 GEMM (R14 config — measured best): C[M,N] = A[M,K] @ Wt[N,K]^T + bias
// 128x128 CTA, BK=64, 8 warps, 3-stage cp.async, 2 CTAs/SM,
// prefetch AFTER compute (measured best placement).
// EPI: 0 bias->fp16 ; 1 bias+relu->fp16 ; 3 bias+res(fp32)->fp16 ;
//      4 bias+res(fp16)->fp32
// ---------------------------------------------------------------------------
#define HTILE_B  16384
#define HSTAGE_B (2 * HTILE_B)
#define HGSMEM   (3 * HSTAGE_B + 128)

template<int EPI>
__device__ __forceinline__ void gemm_core_h(
        const __half* __restrict__ A, const __half* __restrict__ Bw,
        const float* __restrict__ bias, const float* __restrict__ resf,
        const __half* __restrict__ res16,
        float* __restrict__ Cf, __half* __restrict__ Hh,
        int M, int N, int K, int m0, int n0, uint32_t base) {
    int tid = threadIdx.x, lane = tid & 31, wid = tid >> 5;
    int warp_m = wid >> 2;
    int warp_n = wid & 3;

    const __half* Ab = A  + (size_t)m0 * K;
    const __half* Bb = Bw + (size_t)n0 * K;

    int amat = lane >> 3, arin = lane & 7;
    int aRow = warp_m * 64 + (amat & 1) * 8 + arin;
    int aChk = amat >> 1;
    int bRow4 = warp_n * 32 + ((lane >> 4) & 1) * 8 + (lane & 7);
    int bChk4 = (lane >> 3) & 1;

    float C[4][4][4];
    #pragma unroll
    for (int i = 0; i < 4; i++)
        #pragma unroll
        for (int j = 0; j < 4; j++)
            #pragma unroll
            for (int r = 0; r < 4; r++) C[i][j][r] = 0.f;

    int NT = K >> 6;

    cpa_tile128(Ab, K, 0, base);
    cpa_tile128(Bb, K, 0, base + HTILE_B);
    CP_COMMIT();
    cpa_tile128(Ab, K, 64, base + HSTAGE_B);
    cpa_tile128(Bb, K, 64, base + HSTAGE_B + HTILE_B);
    CP_COMMIT();

    for (int kt = 0; kt < NT; kt++) {
        if (kt + 1 < NT) { CP_WAIT1(); } else { CP_WAIT0(); }
        __syncthreads();

        uint32_t sc = base + (kt % 3) * HSTAGE_B;
        uint32_t sA = sc, sB = sc + HTILE_B;

        #pragma unroll
        for (int ks = 0; ks < 4; ks++) {
            uint32_t a4[4][4], b4[2][4];
            #pragma unroll
            for (int mi = 0; mi < 4; mi++) {
                uint32_t off = (uint32_t)((aRow + mi * 16) * 128 + (aChk + ks * 2) * 16);
                off ^= (off >> 3) & 0x70;
                ldm_x4(a4[mi], sA + off);
            }
            #pragma unroll
            for (int ni2 = 0; ni2 < 2; ni2++) {
                uint32_t off = (uint32_t)((bRow4 + ni2 * 16) * 128 + (bChk4 + ks * 2) * 16);
                off ^= (off >> 3) & 0x70;
                ldm_x4(b4[ni2], sB + off);
            }
            #pragma unroll
            for (int mi = 0; mi < 4; mi++) {
                #pragma unroll
                for (int ni2 = 0; ni2 < 2; ni2++) {
                    mma16816h(C[mi][2 * ni2],     a4[mi], &b4[ni2][0]);
                    mma16816h(C[mi][2 * ni2 + 1], a4[mi], &b4[ni2][2]);
                }
            }
        }

        if (kt + 2 < NT) {
            uint32_t sn = base + ((kt + 2) % 3) * HSTAGE_B;
            int k0 = (kt + 2) << 6;
            cpa_tile128(Ab, K, k0, sn);
            cpa_tile128(Bb, K, k0, sn + HTILE_B);
            CP_COMMIT();
        }
    }

    int gq = lane >> 2, tig = lane & 3;
    #pragma unroll
    for (int mi = 0; mi < 4; mi++) {
        #pragma unroll
        for (int ni = 0; ni < 4; ni++) {
            int m = m0 + warp_m * 64 + mi * 16 + gq;
            int n = n0 + warp_n * 32 + ni * 8 + tig * 2;
            float2 bv = *reinterpret_cast<const float2*>(&bias[n]);
            #pragma unroll
            for (int half_ = 0; half_ < 2; half_++) {
                int row = m + half_ * 8;
                float a0 = C[mi][ni][half_ * 2 + 0] + bv.x;
                float a1 = C[mi][ni][half_ * 2 + 1] + bv.y;
                size_t o = (size_t)row * N + n;
                if (EPI == 0) {
                    *reinterpret_cast<uint32_t*>(Hh + o) = pack_h2(a0, a1);
                } else if (EPI == 1) {
                    a0 = fmaxf(a0, 0.f); a1 = fmaxf(a1, 0.f);
                    *reinterpret_cast<uint32_t*>(Hh + o) = pack_h2(a0, a1);
                } else if (EPI == 3) {
                    float2 rv = *reinterpret_cast<const float2*>(&resf[o]);
                    a0 += rv.x; a1 += rv.y;
                    *reinterpret_cast<uint32_t*>(Hh + o) = pack_h2(a0, a1);
                } else {  // EPI == 4
                    uint32_t rp = *reinterpret_cast<const uint32_t*>(&res16[o]);
                    float2 rv = __half22float2(*reinterpret_cast<__half2*>(&rp));
                    a0 += rv.x; a1 += rv.y;
                    *reinterpret_cast<float2*>(&Cf[o]) = make_float2(a0, a1);
                }
            }
        }
    }
}

template<int EPI>
__global__ __launch_bounds__(256, 2)
void hgemm_kernel(const __half* __restrict__ A, const __half* __restrict__ Bw,
                  const float* __restrict__ bias, const float* __restrict__ resf,
                  const __half* __restrict__ res16,
                  float* __restrict__ Cf, __half* __restrict__ Hh,
                  int M, int N, int K) {
    extern __shared__ char dsm[];
    uint32_t base = smem_u32(dsm);
    base = (base + 127) & ~127u;
    gemm_core_h<EPI>(A, Bw, bias, resf, res16, Cf, Hh, M, N, K,
                     blockIdx.y * 128, blockIdx.x * 128, base);
}

struct QKVArgs {
    const __half* w[3];
    const float* bias[3];
    __half* o[3];
};

__global__ __launch_bounds__(256, 2)
void qkv_kernel(const __half* __restrict__ A, QKVArgs args) {
    extern __shared__ char dsm[];
    uint32_t base = smem_u32(dsm);
    base = (base + 127) & ~127u;
    int z = blockIdx.z;
    gemm_core_h<0>(A, args.w[z], args.bias[z], nullptr, nullptr, nullptr,
                   args.o[z], M_, E_, E_,
                   blockIdx.y * 128, blockIdx.x * 128, base);
}

// ---------------------------------------------------------------------------
// fp16 tensor-core causal flash attention (R14 config — measured best).
// q-tile 128, 8 warps, 128-key k-tiles processed as two 64-col halves
// (registers reused), 3-stage KV pipe, 2 CTA/SM, no running max.
// smem: Q 16KB + 3 x (K 16KB + V 16KB) = 112KB.
// ---------------------------------------------------------------------------
#define AQ_BYTES  16384
#define AST_SZ    32768            // K 16KB + V 16KB (128 rows each)
#define ATTN_SMEM (AQ_BYTES + 3 * AST_SZ + 128)
#define CEXP 0.18033688011112042f  // 0.125 * log2(e)

__global__ __launch_bounds__(256, 2)
void attn_mma_kernel(const __half* __restrict__ Qg, const __half* __restrict__ Kg,
                     const __half* __restrict__ Vg, __half* __restrict__ O) {
    extern __shared__ char dsm[];
    uint32_t base = smem_u32(dsm);
    base = (base + 127) & ~127u;

    int tid = threadIdx.x, lane = tid & 31, w = tid >> 5;
    int gq = lane >> 2, tig = lane & 3;
    int qi = gridDim.x - 1 - blockIdx.x;
    int q0 = qi * 128;
    int bh = blockIdx.y;
    int b = bh >> 4, h = bh & 15;
    size_t gbase = ((size_t)b * T_) * E_ + (size_t)h * HS_;

    int nt = (q0 >> 7) + 1;   // 128-key tiles covering [0, q0+128)

    cpa_tile128(Qg + gbase + (size_t)q0 * E_, E_, 0, base);
    CP_COMMIT();
    int pre = nt < 2 ? nt : 2;
    for (int st = 0; st < pre; st++) {
        uint32_t s = base + AQ_BYTES + st * AST_SZ;
        size_t koff = gbase + (size_t)(st * 128) * E_;
        cpa_tile128(Kg + koff, E_, 0, s);
        cpa_tile128(Vg + koff, E_, 0, s + 16384);
        CP_COMMIT();
    }

    if (pre == 2) { CP_WAIT2(); } else { CP_WAIT1(); }
    __syncthreads();

    uint32_t qf[4][4];
    {
        int arow = w * 16 + (lane & 7) + ((lane & 8) ? 8 : 0);
        int asel = (lane >> 4) & 1;
        #pragma unroll
        for (int ks = 0; ks < 4; ks++) {
            uint32_t off = (uint32_t)(arow * 128 + (ks * 2 + asel) * 16);
            off ^= (off >> 3) & 0x70;
            ldm_x4(qf[ks], base + off);
        }
    }

    float Oa[8][4];
    #pragma unroll
    for (int s = 0; s < 8; s++)
        #pragma unroll
        for (int r = 0; r < 4; r++) Oa[s][r] = 0.f;
    float l0r = 0.f, l1r = 0.f;

    int kRowBase = (lane & 7) + ((lane >= 16) ? 8 : 0);
    int kChkSel  = (lane & 8) ? 1 : 0;
    int vRowBase = (lane & 7) + ((lane & 8) ? 8 : 0);
    int vColB    = ((lane >= 16) ? 16 : 0);

    for (int jt = 0; jt < nt; jt++) {
        if (jt + 1 < nt) { CP_WAIT1(); } else { CP_WAIT0(); }
        __syncthreads();

        uint32_t sc = base + AQ_BYTES + (jt % 3) * AST_SZ;
        uint32_t sK = sc, sV = sc + 16384;
        bool edge = (jt == nt - 1);

        #pragma unroll
        for (int h2 = 0; h2 < 2; h2++) {
            // last tile, upper half: warps 0-3 fully masked
            if (edge && h2 == 1 && w < 4) continue;
            int rowOff = h2 * 64;

            float S[8][4];
            #pragma unroll
            for (int s = 0; s < 8; s++)
                #pragma unroll
                for (int r = 0; r < 4; r++) S[s][r] = 0.f;

            #pragma unroll
            for (int ks = 0; ks < 4; ks++) {
                #pragma unroll
                for (int g = 0; g < 4; g++) {
                    uint32_t k4[4];
                    uint32_t off = (uint32_t)((rowOff + g * 16 + kRowBase) * 128 +
                                              (ks * 2 + kChkSel) * 16);
                    off ^= (off >> 3) & 0x70;
                    ldm_x4(k4, sK + off);
                    mma16816h(S[2 * g],     qf[ks], &k4[0]);
                    mma16816h(S[2 * g + 1], qf[ks], &k4[2]);
                }
            }

            if (edge) {
                int qr0 = q0 + w * 16 + gq;
                int kc0 = jt * 128 + rowOff + 2 * tig;
                #pragma unroll
                for (int s = 0; s < 8; s++) {
                    int kc = kc0 + s * 8;
                    if (kc     > qr0)     S[s][0] = -1e30f;
                    if (kc + 1 > qr0)     S[s][1] = -1e30f;
                    if (kc     > qr0 + 8) S[s][2] = -1e30f;
                    if (kc + 1 > qr0 + 8) S[s][3] = -1e30f;
                }
            }

            uint32_t pa[4][4];
            float ls0 = 0.f, ls1 = 0.f;
            #pragma unroll
            for (int kk = 0; kk < 4; kk++) {
                #pragma unroll
                for (int half_ = 0; half_ < 2; half_++) {
                    float* Sr = S[2 * kk + half_];
                    __half2 e0 = h2exp2(__floats2half2_rn(Sr[0] * CEXP, Sr[1] * CEXP));
                    __half2 e1 = h2exp2(__floats2half2_rn(Sr[2] * CEXP, Sr[3] * CEXP));
                    pa[kk][half_ * 2 + 0] = *reinterpret_cast<uint32_t*>(&e0);
                    pa[kk][half_ * 2 + 1] = *reinterpret_cast<uint32_t*>(&e1);
                    float2 f0 = __half22float2(e0);
                    float2 f1 = __half22float2(e1);
                    ls0 += f0.x + f0.y;
                    ls1 += f1.x + f1.y;
                }
            }
            l0r += ls0;
            l1r += ls1;

            #pragma unroll
            for (int kk = 0; kk < 4; kk++) {
                #pragma unroll
                for (int g = 0; g < 4; g++) {
                    uint32_t v4[4];
                    uint32_t off = (uint32_t)((rowOff + kk * 16 + vRowBase) * 128 +
                                              g * 32 + vColB);
                    off ^= (off >> 3) & 0x70;
                    ldm_x4_t(v4, sV + off);
                    mma16816h(Oa[2 * g],     pa[kk], &v4[0]);
                    mma16816h(Oa[2 * g + 1], pa[kk], &v4[2]);
                }
            }
        }

        if (jt + 2 < nt) {
            uint32_t sn = base + AQ_BYTES + ((jt + 2) % 3) * AST_SZ;
            size_t koff = gbase + (size_t)((jt + 2) * 128) * E_;
            cpa_tile128(Kg + koff, E_, 0, sn);
            cpa_tile128(Vg + koff, E_, 0, sn + 16384);
            CP_COMMIT();
        }
    }

    l0r += __shfl_xor_sync(0xffffffffu, l0r, 1);
    l0r += __shfl_xor_sync(0xffffffffu, l0r, 2);
    l1r += __shfl_xor_sync(0xffffffffu, l1r, 1);
    l1r += __shfl_xor_sync(0xffffffffu, l1r, 2);

    float inv0 = 1.0f / l0r, inv1 = 1.0f / l1r;
    int row0 = q0 + w * 16 + gq;
    #pragma unroll
    for (int s = 0; s < 8; s++) {
        int col = s * 8 + 2 * tig;
        size_t o0 = gbase + (size_t)row0 * E_ + col;
        size_t o1 = gbase + (size_t)(row0 + 8) * E_ + col;
        *reinterpret_cast<uint32_t*>(O + o0) = pack_h2(Oa[s][0] * inv0, Oa[s][1] * inv0);
        *reinterpret_cast<uint32_t*>(O + o1) = pack_h2(Oa[s][2] * inv1, Oa[s][3] * inv1);
    }
}

// ---------------------------------------------------------------------------
// Launch
// ---------------------------------------------------------------------------
extern "C" void kernel_launch(void* const* d_in, const int* in_sizes, int n_in,
                              void* d_out, int out_size) {
    (void)in_sizes; (void)n_in; (void)out_size;
    const float* x     = (const float*)d_in[0];
    const float* ln1_g = (const float*)d_in[1];
    const float* ln1_b = (const float*)d_in[2];
    const float* Wq    = (const float*)d_in[3];
    const float* bq    = (const float*)d_in[4];
    const float* Wk    = (const float*)d_in[5];
    const float* bk    = (const float*)d_in[6];
    const float* Wv    = (const float*)d_in[7];
    const float* bv    = (const float*)d_in[8];
    const float* Wp    = (const float*)d_in[9];
    const float* bp    = (const float*)d_in[10];
    const float* ln2_g = (const float*)d_in[11];
    const float* ln2_b = (const float*)d_in[12];
    const float* W1    = (const float*)d_in[13];
    const float* b1    = (const float*)d_in[14];
    const float* W2    = (const float*)d_in[15];
    const float* b2    = (const float*)d_in[16];
    float* out = (float*)d_out;

    __half *a, *f, *q, *k, *v, *wq, *wk, *wv, *wp, *w1, *w2;
    cudaGetSymbolAddress((void**)&a, g_a);
    cudaGetSymbolAddress((void**)&f, g_f);
    cudaGetSymbolAddress((void**)&q, g_q);
    cudaGetSymbolAddress((void**)&k, g_k);
    cudaGetSymbolAddress((void**)&v, g_v);
    cudaGetSymbolAddress((void**)&wq, g_wq);
    cudaGetSymbolAddress((void**)&wk, g_wk);
    cudaGetSymbolAddress((void**)&wv, g_wv);
    cudaGetSymbolAddress((void**)&wp, g_wp);
    cudaGetSymbolAddress((void**)&w1, g_w1);
    cudaGetSymbolAddress((void**)&w2, g_w2);

    __half* r1 = q;   // fp16 residual stream (g_q free after attention)

    cudaFuncSetAttribute(attn_mma_kernel,
                         cudaFuncAttributeMaxDynamicSharedMemorySize, ATTN_SMEM);
    cudaFuncSetAttribute(hgemm_kernel<1>,
                         cudaFuncAttributeMaxDynamicSharedMemorySize, HGSMEM);
    cudaFuncSetAttribute(hgemm_kernel<3>,
                         cudaFuncAttributeMaxDynamicSharedMemorySize, HGSMEM);
    cudaFuncSetAttribute(hgemm_kernel<4>,
                         cudaFuncAttributeMaxDynamicSharedMemorySize, HGSMEM);
    cudaFuncSetAttribute(qkv_kernel,
                         cudaFuncAttributeMaxDynamicSharedMemorySize, HGSMEM);

    // fused prep: weight transposes + ln1 in one launch
    PrepArgs pa;
    pa.src[0] = Wq; pa.dst[0] = wq; pa.K[0] = E_;   pa.N[0] = E_;   pa.base[0] = 0;    pa.nx[0] = 16;
    pa.src[1] = Wk; pa.dst[1] = wk; pa.K[1] = E_;   pa.N[1] = E_;   pa.base[1] = 256;  pa.nx[1] = 16;
    pa.src[2] = Wv; pa.dst[2] = wv; pa.K[2] = E_;   pa.N[2] = E_;   pa.base[2] = 512;  pa.nx[2] = 16;
    pa.src[3] = Wp; pa.dst[3] = wp; pa.K[3] = E_;   pa.N[3] = E_;   pa.base[3] = 768;  pa.nx[3] = 16;
    pa.src[4] = W1; pa.dst[4] = w1; pa.K[4] = E_;   pa.N[4] = DFF_; pa.base[4] = 1024; pa.nx[4] = 64;
    pa.src[5] = W2; pa.dst[5] = w2; pa.K[5] = DFF_; pa.N[5] = E_;   pa.base[5] = 2048; pa.nx[5] = 16;
    pa.x = x; pa.ln_g = ln1_g; pa.ln_b = ln1_b; pa.ln_o = a;
    prep_kernel<<<WT_BLOCKS + M_, 256>>>(pa);

    // fused QKV
    QKVArgs qa;
    qa.w[0] = wq; qa.bias[0] = bq; qa.o[0] = q;
    qa.w[1] = wk; qa.bias[1] = bk; qa.o[1] = k;
    qa.w[2] = wv; qa.bias[2] = bv; qa.o[2] = v;
    dim3 gQKV(E_ / 128, M_ / 128, 3);
    qkv_kernel<<<gQKV, 256, HGSMEM>>>(a, qa);

    // attention -> a
    dim3 gA(T_ / 128, B_ * H_);
    attn_mma_kernel<<<gA, 256, ATTN_SMEM>>>(q, k, v, a);

    // proj + residual(x fp32) -> r1 (fp16 residual stream)
    dim3 gE(E_ / 128, M_ / 128);
    hgemm_kernel<3><<<gE, 256, HGSMEM>>>(a, wp, bp, x, nullptr, nullptr, r1,
                                         M_, E_, E_);

    // ln2 (fp16 in) -> fp16
    ln_h16_kernel<<<M_, 256>>>(r1, ln2_g, ln2_b, a);

    // FFN1 (relu -> fp16)
    dim3 gF1(DFF_ / 128, M_ / 128);
    hgemm_kernel<1><<<gF1, 256, HGSMEM>>>(a, w1, b1, nullptr, nullptr, nullptr, f,
                                          M_, DFF_, E_);

    // FFN2 + residual(r1 fp16) -> out (fp32)
    hgemm_kernel<4><<<gE, 256, HGSMEM>>>(f, w2, b2, nullptr, r1, out, nullptr,
                                         M_, E_, DFF_);
}